// round 10
// baseline (speedup 1.0000x reference)
#include <cuda_runtime.h>
#include <cuda_bf16.h>

// Problem constants (B=2, T=256, E=256, H=4)
#define E_DIM  256
#define EH_DIM 1024
#define BT_DIM 512
#define SPLITK 16
#define PCHUNK 64           // EH_DIM / SPLITK
#define KSTEP  16
#define GRID   256          // must be <= 296 (2 CTAs/SM co-residency bound)

typedef unsigned long long u64;

// Packed fp32x2 helpers (sm_100+): one instruction, two fp32 FMAs.
#define PACK2(d, lo, hi) asm("mov.b64 %0, {%1, %2};" : "=l"(d) : "f"(lo), "f"(hi))
#define FMA2(d, a, b)    asm("fma.rn.f32x2 %0, %1, %2, %0;" : "+l"(d) : "l"(a), "l"(b))
#define UNPACK2(lo, hi, s) asm("mov.b64 {%0, %1}, %2;" : "=f"(lo), "=f"(hi) : "l"(s))

// Split-K partials for C[f][e] (plain stores -> deterministic), then reduced.
__device__ float g_Cp[SPLITK][E_DIM * E_DIM];   // 4 MB
__device__ float g_C[E_DIM * E_DIM];            // 256 KB

// Device-wide barrier state. g_cnt self-resets each use; g_epoch is monotonic
// across graph replays (each wait compares against its pre-arrival snapshot).
__device__ unsigned g_cnt[2];
__device__ unsigned g_epoch[2];

__device__ __forceinline__ void grid_barrier(int slot)
{
    __syncthreads();
    if (threadIdx.x == 0) {
        volatile unsigned* ep = &g_epoch[slot];
        unsigned my = *ep;                       // snapshot BEFORE arriving
        __threadfence();                         // publish this CTA's writes
        unsigned t = atomicAdd(&g_cnt[slot], 1u);
        if (t == GRID - 1) {
            g_cnt[slot] = 0;                     // all arrived; safe to reset
            __threadfence();
            atomicAdd(&g_epoch[slot], 1u);       // release
        } else {
            while (*ep == my) __nanosleep(32);
        }
    }
    __syncthreads();
}

// Shared memory: union of phase-1 GEMM tiles and phase-3 GEMM tiles.
union SmemU {
    struct { float A[KSTEP][64]; float B[KSTEP][68]; } p1;   // 8448 B
    struct { float V[16][34];    float C[16][34];    } p3;   // 4352 B
};

// ---------------------------------------------------------------------------
// ONE persistent kernel, three phases, two device-wide barriers.
//   Phase 1: C[f,e] partials.  C = sum_p Wv[c(p),f] * Wp[e,p],
//            p = d*H+h (Wp-native), c(p) = (p&3)*256 + (p>>2).
//            16 tiles (64x64) x 16 k-splits = 256 work units (1 per CTA).
//   Phase 2: g_C = sum_z g_Cp[z]  (fixed order -> deterministic).
//   Phase 3: out[m,e] = sum_f values[m,f] * g_C[f,e]  (128 CTA units).
// ---------------------------------------------------------------------------
__global__ __launch_bounds__(256, 2) void fused_kernel(
    const float* __restrict__ values,   // [BT, E]
    const float* __restrict__ Wv,       // [EH, E]
    const float* __restrict__ Wp,       // [E, EH]
    float* __restrict__ out)            // [BT, E]
{
    __shared__ __align__(16) SmemU sm;

    const int tid = threadIdx.x;
    const int cta = blockIdx.x;

    // ================= Phase 1: build C partials =================
    {
        const int tileId = cta & 15;
        const int kz     = cta >> 4;           // 0..15
        const int f0 = (tileId & 3) * 64;
        const int e0 = (tileId >> 2) * 64;
        const int p0 = kz * PCHUNK;

        const int tx = tid & 15;               // f group
        const int ty = tid >> 4;               // e group

        u64 acc01[4], acc23[4];
        #pragma unroll
        for (int j = 0; j < 4; j++) { PACK2(acc01[j], 0.f, 0.f); PACK2(acc23[j], 0.f, 0.f); }

        const int lA_pc = tid >> 4;            // 0..15
        const int lA_f4 = (tid & 15) * 4;
        const int lB_e  = tid >> 2;            // 0..63
        const int lB_p4 = (tid & 3) * 4;

        // prefetch k-tile 0
        float4 pa, pb;
        {
            int p = p0 + lA_pc;
            int c = ((p & 3) << 8) + (p >> 2);
            pa = *(const float4*)&Wv[c * E_DIM + f0 + lA_f4];
            pb = *(const float4*)&Wp[(e0 + lB_e) * EH_DIM + p0 + lB_p4];
        }

        #pragma unroll
        for (int it = 0; it < PCHUNK / KSTEP; it++) {
            *(float4*)&sm.p1.A[lA_pc][lA_f4] = pa;
            sm.p1.B[lB_p4 + 0][lB_e] = pb.x;
            sm.p1.B[lB_p4 + 1][lB_e] = pb.y;
            sm.p1.B[lB_p4 + 2][lB_e] = pb.z;
            sm.p1.B[lB_p4 + 3][lB_e] = pb.w;
            __syncthreads();

            if (it < PCHUNK / KSTEP - 1) {     // prefetch next tile
                int p = p0 + (it + 1) * KSTEP + lA_pc;
                int c = ((p & 3) << 8) + (p >> 2);
                pa = *(const float4*)&Wv[c * E_DIM + f0 + lA_f4];
                pb = *(const float4*)&Wp[(e0 + lB_e) * EH_DIM + p0 + (it + 1) * KSTEP + lB_p4];
            }

            #pragma unroll
            for (int ps = 0; ps < KSTEP; ps++) {
                float4 a = *(float4*)&sm.p1.A[ps][tx * 4];
                float4 b = *(float4*)&sm.p1.B[ps][ty * 4];
                u64 a01, a23, bd0, bd1, bd2, bd3;
                PACK2(a01, a.x, a.y);
                PACK2(a23, a.z, a.w);
                PACK2(bd0, b.x, b.x); FMA2(acc01[0], a01, bd0); FMA2(acc23[0], a23, bd0);
                PACK2(bd1, b.y, b.y); FMA2(acc01[1], a01, bd1); FMA2(acc23[1], a23, bd1);
                PACK2(bd2, b.z, b.z); FMA2(acc01[2], a01, bd2); FMA2(acc23[2], a23, bd2);
                PACK2(bd3, b.w, b.w); FMA2(acc01[3], a01, bd3); FMA2(acc23[3], a23, bd3);
            }
            __syncthreads();
        }

        // epilogue: 4 x STG.128
        float r[4][4];
        #pragma unroll
        for (int j = 0; j < 4; j++) {
            UNPACK2(r[0][j], r[1][j], acc01[j]);
            UNPACK2(r[2][j], r[3][j], acc23[j]);
        }
        float* dst = &g_Cp[kz][0];
        #pragma unroll
        for (int i = 0; i < 4; i++) {
            int f = f0 + tx * 4 + i;
            *(float4*)&dst[f * E_DIM + e0 + ty * 4] =
                make_float4(r[i][0], r[i][1], r[i][2], r[i][3]);
        }
    }

    grid_barrier(0);

    // ================= Phase 2: reduce partials =================
    {
        int gid = cta * 256 + tid;             // 65536 threads; 16384 active
        if (gid < (E_DIM * E_DIM) / 4) {
            int idx4 = gid * 4;
            float4 s = make_float4(0.f, 0.f, 0.f, 0.f);
            #pragma unroll
            for (int z0 = 0; z0 < SPLITK; z0 += 8) {
                float4 v[8];
                #pragma unroll
                for (int z = 0; z < 8; z++)
                    v[z] = *(const float4*)&g_Cp[z0 + z][idx4];
                #pragma unroll
                for (int z = 0; z < 8; z++) {
                    s.x += v[z].x; s.y += v[z].y; s.z += v[z].z; s.w += v[z].w;
                }
            }
            *(float4*)&g_C[idx4] = s;
        }
    }

    grid_barrier(1);

    // ================= Phase 3: out = values @ C =================
    if (cta < 128) {
        const int e0 = (cta & 7) * 32;
        const int m0 = (cta >> 3) * 32;
        const int tx = tid & 15;               // e pair
        const int ty = tid >> 4;               // m pair

        u64 accj0, accj1;
        PACK2(accj0, 0.f, 0.f);
        PACK2(accj1, 0.f, 0.f);

        const int lV_m  = tid >> 3;
        const int lV_f2 = (tid & 7) * 2;
        const int lC_f  = tid >> 4;
        const int lC_e2 = (tid & 15) * 2;

        float2 pv = *(const float2*)&values[(m0 + lV_m) * E_DIM + lV_f2];
        float2 pc = *(const float2*)&g_C[lC_f * E_DIM + e0 + lC_e2];

        #pragma unroll
        for (int it = 0; it < E_DIM / 16; it++) {
            sm.p3.V[lV_f2][lV_m]     = pv.x;   // transposed store
            sm.p3.V[lV_f2 + 1][lV_m] = pv.y;
            *(float2*)&sm.p3.C[lC_f][lC_e2] = pc;
            __syncthreads();

            if (it < E_DIM / 16 - 1) {
                int f0 = (it + 1) * 16;
                pv = *(const float2*)&values[(m0 + lV_m) * E_DIM + f0 + lV_f2];
                pc = *(const float2*)&g_C[(f0 + lC_f) * E_DIM + e0 + lC_e2];
            }

            #pragma unroll
            for (int ps = 0; ps < 16; ps++) {
                float2 a = *(float2*)&sm.p3.V[ps][ty * 2];
                float2 b = *(float2*)&sm.p3.C[ps][tx * 2];
                u64 a01, bd0, bd1;
                PACK2(a01, a.x, a.y);
                PACK2(bd0, b.x, b.x); FMA2(accj0, a01, bd0);
                PACK2(bd1, b.y, b.y); FMA2(accj1, a01, bd1);
            }
            __syncthreads();
        }

        float o00, o10, o01, o11;
        UNPACK2(o00, o10, accj0);
        UNPACK2(o01, o11, accj1);
        *(float2*)&out[(m0 + ty * 2) * E_DIM + e0 + tx * 2]     = make_float2(o00, o01);
        *(float2*)&out[(m0 + ty * 2 + 1) * E_DIM + e0 + tx * 2] = make_float2(o10, o11);
    }
}

// ---------------------------------------------------------------------------
// softmax over w sums to 1 => out = Vh; only values, Wv, Wp matter.
// Inputs: 0=pos_emb, 1=values, 2=ln_w, 3=ln_b, 4=Wq, 5=Wk, 6=Wv, 7=Wp.
// ---------------------------------------------------------------------------
extern "C" void kernel_launch(void* const* d_in, const int* in_sizes, int n_in,
                              void* d_out, int out_size)
{
    const float* values = (const float*)d_in[1];
    const float* Wv     = (const float*)d_in[6];
    const float* Wp     = (const float*)d_in[7];
    float* out          = (float*)d_out;

    fused_kernel<<<GRID, 256>>>(values, Wv, Wp, out);
}

// round 11
// speedup vs baseline: 1.0831x; 1.0831x over previous
#include <cuda_runtime.h>
#include <cuda_bf16.h>

// Problem constants (B=2, T=256, E=256, H=4)
#define E_DIM  256
#define EH_DIM 1024
#define BT_DIM 512
#define SPLITK 16
#define PCHUNK 64           // EH_DIM / SPLITK
#define KSTEP  16
#define NTILE  16           // 4x4 tiles of 64x64 over C

typedef unsigned long long u64;

// Packed fp32x2 helpers (sm_100+): one instruction, two fp32 FMAs.
#define PACK2(d, lo, hi) asm("mov.b64 %0, {%1, %2};" : "=l"(d) : "f"(lo), "f"(hi))
#define FMA2(d, a, b)    asm("fma.rn.f32x2 %0, %1, %2, %0;" : "+l"(d) : "l"(a), "l"(b))
#define UNPACK2(lo, hi, s) asm("mov.b64 {%0, %1}, %2;" : "=f"(lo), "=f"(hi) : "l"(s))

// Split-K partials, tile-contiguous: g_Cp[tile][z][f_loc*64 + e_loc].
__device__ float    g_Cp[NTILE][SPLITK][64 * 64];   // 4 MB
__device__ float    g_C[E_DIM * E_DIM];             // 256 KB
__device__ unsigned g_tick[NTILE];                  // fan-in tickets (self-reset)

// ---------------------------------------------------------------------------
// Kernel 1: C partials + in-kernel fan-in reduction.
//   C[f,e] = sum_p Wv[c(p),f] * Wp[e,p],  p = d*H+h,  c(p) = (p&3)*256+(p>>2).
//   grid 256 = 16 tiles x 16 k-splits.  64x64 tile, 4x4 micro (f32x2).
//   The 16th CTA to finish a tile sums its 16 partials (fixed z order ->
//   deterministic) and writes g_C.  No reduce kernel, no grid barrier.
// ---------------------------------------------------------------------------
__global__ __launch_bounds__(256) void build_C_kernel(
    const float* __restrict__ Wv,   // [EH, E] row-major
    const float* __restrict__ Wp)   // [E, EH] row-major
{
    __shared__ __align__(16) float sA[KSTEP][64];   // [p_local][f_local]
    __shared__ __align__(16) float sB[KSTEP][68];   // [p_local][e_local] (pad)
    __shared__ unsigned sTicket;

    const int tid    = threadIdx.x;
    const int tileId = blockIdx.x & 15;
    const int kz     = blockIdx.x >> 4;      // 0..15
    const int f0 = (tileId & 3) * 64;
    const int e0 = (tileId >> 2) * 64;
    const int p0 = kz * PCHUNK;

    const int tx = tid & 15;                 // f group
    const int ty = tid >> 4;                 // e group

    u64 acc01[4], acc23[4];
    #pragma unroll
    for (int j = 0; j < 4; j++) { PACK2(acc01[j], 0.f, 0.f); PACK2(acc23[j], 0.f, 0.f); }

    const int lA_pc = tid >> 4;              // 0..15
    const int lA_f4 = (tid & 15) * 4;
    const int lB_e  = tid >> 2;              // 0..63
    const int lB_p4 = (tid & 3) * 4;

    // prefetch k-tile 0
    float4 pa, pb;
    {
        int p = p0 + lA_pc;
        int c = ((p & 3) << 8) + (p >> 2);
        pa = *(const float4*)&Wv[c * E_DIM + f0 + lA_f4];
        pb = *(const float4*)&Wp[(e0 + lB_e) * EH_DIM + p0 + lB_p4];
    }

    #pragma unroll
    for (int it = 0; it < PCHUNK / KSTEP; it++) {
        *(float4*)&sA[lA_pc][lA_f4] = pa;
        sB[lB_p4 + 0][lB_e] = pb.x;
        sB[lB_p4 + 1][lB_e] = pb.y;
        sB[lB_p4 + 2][lB_e] = pb.z;
        sB[lB_p4 + 3][lB_e] = pb.w;
        __syncthreads();

        if (it < PCHUNK / KSTEP - 1) {       // prefetch next tile under compute
            int p = p0 + (it + 1) * KSTEP + lA_pc;
            int c = ((p & 3) << 8) + (p >> 2);
            pa = *(const float4*)&Wv[c * E_DIM + f0 + lA_f4];
            pb = *(const float4*)&Wp[(e0 + lB_e) * EH_DIM + p0 + (it + 1) * KSTEP + lB_p4];
        }

        #pragma unroll
        for (int ps = 0; ps < KSTEP; ps++) {
            float4 a = *(float4*)&sA[ps][tx * 4];
            float4 b = *(float4*)&sB[ps][ty * 4];
            u64 a01, a23, bd0, bd1, bd2, bd3;
            PACK2(a01, a.x, a.y);
            PACK2(a23, a.z, a.w);
            PACK2(bd0, b.x, b.x); FMA2(acc01[0], a01, bd0); FMA2(acc23[0], a23, bd0);
            PACK2(bd1, b.y, b.y); FMA2(acc01[1], a01, bd1); FMA2(acc23[1], a23, bd1);
            PACK2(bd2, b.z, b.z); FMA2(acc01[2], a01, bd2); FMA2(acc23[2], a23, bd2);
            PACK2(bd3, b.w, b.w); FMA2(acc01[3], a01, bd3); FMA2(acc23[3], a23, bd3);
        }
        __syncthreads();
    }

    // store partial, tile-contiguous: [f_loc*64 + e_loc]
    {
        float r[4][4];
        #pragma unroll
        for (int j = 0; j < 4; j++) {
            UNPACK2(r[0][j], r[1][j], acc01[j]);
            UNPACK2(r[2][j], r[3][j], acc23[j]);
        }
        float* dst = &g_Cp[tileId][kz][0];
        #pragma unroll
        for (int i = 0; i < 4; i++) {
            *(float4*)&dst[(tx * 4 + i) * 64 + ty * 4] =
                make_float4(r[i][0], r[i][1], r[i][2], r[i][3]);
        }
    }

    // --- fan-in: last CTA for this tile reduces the 16 partials ---
    __threadfence();                         // publish this CTA's partial
    __syncthreads();                         // all threads' fences done
    if (tid == 0)
        sTicket = atomicAdd(&g_tick[tileId], 1u);
    __syncthreads();
    if (sTicket != SPLITK - 1) return;       // not the last arrival

    __threadfence();                         // acquire: see all partials
    if (tid == 0) g_tick[tileId] = 0;        // reset for next graph replay

    // 256 threads x 4 float4 positions, z summed in fixed order (deterministic)
    const float* src = &g_Cp[tileId][0][0];
    #pragma unroll
    for (int j = 0; j < 4; j++) {
        int i4 = tid * 16 + j * 4;           // tile-local element index
        float4 s = make_float4(0.f, 0.f, 0.f, 0.f);
        #pragma unroll
        for (int z0 = 0; z0 < SPLITK; z0 += 8) {
            float4 v[8];
            #pragma unroll
            for (int z = 0; z < 8; z++)
                v[z] = *(const float4*)&src[(z0 + z) * 4096 + i4];
            #pragma unroll
            for (int z = 0; z < 8; z++) {
                s.x += v[z].x; s.y += v[z].y; s.z += v[z].z; s.w += v[z].w;
            }
        }
        int f_loc = i4 >> 6;
        int e_loc = i4 & 63;
        *(float4*)&g_C[(f0 + f_loc) * E_DIM + e0 + e_loc] = s;
    }
}

// ---------------------------------------------------------------------------
// Kernel 2: out[m,e] = sum_f values[m,f] * C[f,e]
// 32x32 tile, 2x2 micro (f32x2 along m), 256 thr, grid (8,16) = 128 CTAs.
// ---------------------------------------------------------------------------
__global__ __launch_bounds__(256) void gemm_out_kernel(
    const float* __restrict__ values,   // [BT, E]
    float* __restrict__ out)            // [BT, E]
{
    __shared__ __align__(8) float sV[16][34];   // [f_local][m]
    __shared__ __align__(8) float sC[16][34];   // [f_local][e]

    const int tid = threadIdx.x;
    const int tx  = tid & 15;      // e pair
    const int ty  = tid >> 4;      // m pair
    const int e0  = blockIdx.x * 32;
    const int m0  = blockIdx.y * 32;

    u64 accj0, accj1;
    PACK2(accj0, 0.f, 0.f);
    PACK2(accj1, 0.f, 0.f);

    const int lV_m  = tid >> 3;
    const int lV_f2 = (tid & 7) * 2;
    const int lC_f  = tid >> 4;
    const int lC_e2 = (tid & 15) * 2;

    float2 pv = *(const float2*)&values[(m0 + lV_m) * E_DIM + lV_f2];
    float2 pc = *(const float2*)&g_C[lC_f * E_DIM + e0 + lC_e2];

    #pragma unroll
    for (int it = 0; it < E_DIM / 16; it++) {
        sV[lV_f2][lV_m]     = pv.x;          // transposed store
        sV[lV_f2 + 1][lV_m] = pv.y;
        *(float2*)&sC[lC_f][lC_e2] = pc;
        __syncthreads();

        if (it < E_DIM / 16 - 1) {
            int f0 = (it + 1) * 16;
            pv = *(const float2*)&values[(m0 + lV_m) * E_DIM + f0 + lV_f2];
            pc = *(const float2*)&g_C[(f0 + lC_f) * E_DIM + e0 + lC_e2];
        }

        #pragma unroll
        for (int ps = 0; ps < 16; ps++) {
            float2 a = *(float2*)&sV[ps][ty * 2];
            float2 b = *(float2*)&sC[ps][tx * 2];
            u64 a01, bd0, bd1;
            PACK2(a01, a.x, a.y);
            PACK2(bd0, b.x, b.x); FMA2(accj0, a01, bd0);
            PACK2(bd1, b.y, b.y); FMA2(accj1, a01, bd1);
        }
        __syncthreads();
    }

    float o00, o10, o01, o11;
    UNPACK2(o00, o10, accj0);
    UNPACK2(o01, o11, accj1);
    *(float2*)&out[(m0 + ty * 2) * E_DIM + e0 + tx * 2]     = make_float2(o00, o01);
    *(float2*)&out[(m0 + ty * 2 + 1) * E_DIM + e0 + tx * 2] = make_float2(o10, o11);
}

// ---------------------------------------------------------------------------
// softmax over w sums to 1 => out = Vh; only values, Wv, Wp matter.
// Inputs: 0=pos_emb, 1=values, 2=ln_w, 3=ln_b, 4=Wq, 5=Wk, 6=Wv, 7=Wp.
// ---------------------------------------------------------------------------
extern "C" void kernel_launch(void* const* d_in, const int* in_sizes, int n_in,
                              void* d_out, int out_size)
{
    const float* values = (const float*)d_in[1];
    const float* Wv     = (const float*)d_in[6];
    const float* Wp     = (const float*)d_in[7];
    float* out          = (float*)d_out;

    build_C_kernel<<<256, 256>>>(Wv, Wp);
    gemm_out_kernel<<<dim3(8, 16), 256>>>(values, out);
}

// round 13
// speedup vs baseline: 1.1635x; 1.0742x over previous
#include <cuda_runtime.h>
#include <cuda_bf16.h>

// Problem constants (B=2, T=256, E=256, H=4)
#define E_DIM  256
#define EH_DIM 1024
#define BT_DIM 512
#define SPLITK 4
#define PCHUNK 256          // EH_DIM / SPLITK
#define KSTEP  32

typedef unsigned long long u64;

// Packed fp32x2 helpers (sm_100+): one instruction, two fp32 FMAs.
#define PACK2(d, lo, hi) asm("mov.b64 %0, {%1, %2};" : "=l"(d) : "f"(lo), "f"(hi))
#define FMA2(d, a, b)    asm("fma.rn.f32x2 %0, %1, %2, %0;" : "+l"(d) : "l"(a), "l"(b))
#define UNPACK2(lo, hi, s) asm("mov.b64 {%0, %1}, %2;" : "=f"(lo), "=f"(hi) : "l"(s))

// Split-K partials of C[f][e]; summed at load time by gemm_out (fixed order).
__device__ float g_Cp[SPLITK][E_DIM * E_DIM];   // 1 MB

// ---------------------------------------------------------------------------
// Kernel 1: C partials.  C[f,e] = sum_p Wv[c(p),f] * Wp[e,p],
//   p = d*H+h (Wp-native), c(p) = (p&3)*256 + (p>>2).  Both loads coalesced.
// 32x32 tile, 2x2 micro (f32x2 along f), 256 thr, grid (8,8,4) = 256 CTAs.
// Per-thread work ~1024 MACs -> very light node, high CTA spread.
// ---------------------------------------------------------------------------
__global__ __launch_bounds__(256) void build_C_kernel(
    const float* __restrict__ Wv,   // [EH, E] row-major
    const float* __restrict__ Wp)   // [E, EH] row-major
{
    __shared__ __align__(16) float sA[KSTEP][32];   // [p_local][f_local]
    __shared__ __align__(16) float sB[KSTEP][33];   // [p_local][e_local] (pad)

    const int tid = threadIdx.x;
    const int tx  = tid & 15;       // e pair (compute)
    const int ty  = tid >> 4;       // f pair (compute)
    const int f0  = blockIdx.x * 32;
    const int e0  = blockIdx.y * 32;
    const int p0  = blockIdx.z * PCHUNK;

    u64 acce0, acce1;               // (f0,f1) packed, for e=2tx and e=2tx+1
    PACK2(acce0, 0.f, 0.f);
    PACK2(acce1, 0.f, 0.f);

    const int lA_pc = tid >> 3;            // 0..31
    const int lA_f4 = (tid & 7) * 4;
    const int lB_e  = tid >> 3;            // 0..31
    const int lB_p4 = (tid & 7) * 4;

    // prefetch k-tile 0
    float4 pa, pb;
    {
        int p = p0 + lA_pc;
        int c = ((p & 3) << 8) + (p >> 2);
        pa = *(const float4*)&Wv[c * E_DIM + f0 + lA_f4];
        pb = *(const float4*)&Wp[(e0 + lB_e) * EH_DIM + p0 + lB_p4];
    }

    #pragma unroll
    for (int it = 0; it < PCHUNK / KSTEP; it++) {
        *(float4*)&sA[lA_pc][lA_f4] = pa;
        sB[lB_p4 + 0][lB_e] = pb.x;     // scatter: banks p4+i+e all distinct
        sB[lB_p4 + 1][lB_e] = pb.y;
        sB[lB_p4 + 2][lB_e] = pb.z;
        sB[lB_p4 + 3][lB_e] = pb.w;
        __syncthreads();

        if (it < PCHUNK / KSTEP - 1) {  // prefetch next tile under compute
            int p = p0 + (it + 1) * KSTEP + lA_pc;
            int c = ((p & 3) << 8) + (p >> 2);
            pa = *(const float4*)&Wv[c * E_DIM + f0 + lA_f4];
            pb = *(const float4*)&Wp[(e0 + lB_e) * EH_DIM + p0 + (it + 1) * KSTEP + lB_p4];
        }

        #pragma unroll
        for (int ps = 0; ps < KSTEP; ps++) {
            float2 a = *(float2*)&sA[ps][ty * 2];   // f pair (broadcast)
            float b0 = sB[ps][tx * 2];              // e pair (stride-1)
            float b1 = sB[ps][tx * 2 + 1];
            u64 a01, bd0, bd1;
            PACK2(a01, a.x, a.y);
            PACK2(bd0, b0, b0); FMA2(acce0, a01, bd0);
            PACK2(bd1, b1, b1); FMA2(acce1, a01, bd1);
        }
        __syncthreads();
    }

    // store partial: rows f0+2ty, f0+2ty+1; cols e0+2tx (float2, semi-coalesced)
    float c00, c10, c01, c11;
    UNPACK2(c00, c10, acce0);
    UNPACK2(c01, c11, acce1);
    float* dst = &g_Cp[blockIdx.z][0];
    *(float2*)&dst[(f0 + ty * 2) * E_DIM + e0 + tx * 2]     = make_float2(c00, c01);
    *(float2*)&dst[(f0 + ty * 2 + 1) * E_DIM + e0 + tx * 2] = make_float2(c10, c11);
}

// ---------------------------------------------------------------------------
// Kernel 2: out[m,e] = sum_f values[m,f] * C[f,e], where C is summed from the
// 4 split-K partials AT LOAD TIME (fixed order -> deterministic, identical in
// every CTA).  32x32 tile, 2x2 micro, 256 thr, grid (8,16) = 128 CTAs.
// ---------------------------------------------------------------------------
__global__ __launch_bounds__(256) void gemm_out_kernel(
    const float* __restrict__ values,   // [BT, E]
    float* __restrict__ out)            // [BT, E]
{
    __shared__ __align__(8) float sV[16][34];   // [f_local][m]
    __shared__ __align__(8) float sC[16][34];   // [f_local][e]

    const int tid = threadIdx.x;
    const int tx  = tid & 15;      // e pair
    const int ty  = tid >> 4;      // m pair
    const int e0  = blockIdx.x * 32;
    const int m0  = blockIdx.y * 32;

    u64 accj0, accj1;
    PACK2(accj0, 0.f, 0.f);
    PACK2(accj1, 0.f, 0.f);

    const int lV_m  = tid >> 3;
    const int lV_f2 = (tid & 7) * 2;
    const int lC_f  = tid >> 4;
    const int lC_e2 = (tid & 15) * 2;

    // load C element pair = sum of 4 partials (MLP-4, L2-hot)
    auto loadC = [&](int fb) -> float2 {
        int off = (fb + lC_f) * E_DIM + e0 + lC_e2;
        float2 c0 = *(const float2*)&g_Cp[0][off];
        float2 c1 = *(const float2*)&g_Cp[1][off];
        float2 c2 = *(const float2*)&g_Cp[2][off];
        float2 c3 = *(const float2*)&g_Cp[3][off];
        return make_float2((c0.x + c1.x) + (c2.x + c3.x),
                           (c0.y + c1.y) + (c2.y + c3.y));
    };

    float2 pv = *(const float2*)&values[(m0 + lV_m) * E_DIM + lV_f2];
    float2 pc = loadC(0);

    #pragma unroll
    for (int it = 0; it < E_DIM / 16; it++) {
        sV[lV_f2][lV_m]     = pv.x;          // transposed store
        sV[lV_f2 + 1][lV_m] = pv.y;
        *(float2*)&sC[lC_f][lC_e2] = pc;
        __syncthreads();

        if (it < E_DIM / 16 - 1) {
            int fb = (it + 1) * 16;
            pv = *(const float2*)&values[(m0 + lV_m) * E_DIM + fb + lV_f2];
            pc = loadC(fb);
        }

        #pragma unroll
        for (int ps = 0; ps < 16; ps++) {
            float2 a = *(float2*)&sV[ps][ty * 2];
            float2 b = *(float2*)&sC[ps][tx * 2];
            u64 a01, bd0, bd1;
            PACK2(a01, a.x, a.y);
            PACK2(bd0, b.x, b.x); FMA2(accj0, a01, bd0);
            PACK2(bd1, b.y, b.y); FMA2(accj1, a01, bd1);
        }
        __syncthreads();
    }

    float o00, o10, o01, o11;
    UNPACK2(o00, o10, accj0);
    UNPACK2(o01, o11, accj1);
    *(float2*)&out[(m0 + ty * 2) * E_DIM + e0 + tx * 2]     = make_float2(o00, o01);
    *(float2*)&out[(m0 + ty * 2 + 1) * E_DIM + e0 + tx * 2] = make_float2(o10, o11);
}

// ---------------------------------------------------------------------------
// softmax over w sums to 1 => out = Vh; only values, Wv, Wp matter.
// Inputs: 0=pos_emb, 1=values, 2=ln_w, 3=ln_b, 4=Wq, 5=Wk, 6=Wv, 7=Wp.
// ---------------------------------------------------------------------------
extern "C" void kernel_launch(void* const* d_in, const int* in_sizes, int n_in,
                              void* d_out, int out_size)
{
    const float* values = (const float*)d_in[1];
    const float* Wv     = (const float*)d_in[6];
    const float* Wp     = (const float*)d_in[7];
    float* out          = (float*)d_out;

    build_C_kernel<<<dim3(8, 8, SPLITK), 256>>>(Wv, Wp);
    gemm_out_kernel<<<dim3(8, 16), 256>>>(values, out);
}

// round 16
// speedup vs baseline: 1.4117x; 1.2133x over previous
#include <cuda_runtime.h>
#include <cuda_bf16.h>

// Problem constants (B=2, T=256, E=256, H=4)
#define E_DIM  256
#define EH_DIM 1024
#define BT_DIM 512
#define SPLITK 16
#define PCHUNK 64           // EH_DIM / SPLITK
#define KSTEP  16

typedef unsigned long long u64;

// Packed fp32x2 helpers (sm_100+): one instruction, two fp32 FMAs.
#define PACK2(d, lo, hi) asm("mov.b64 %0, {%1, %2};" : "=l"(d) : "f"(lo), "f"(hi))
#define FMA2(d, a, b)    asm("fma.rn.f32x2 %0, %1, %2, %0;" : "+l"(d) : "l"(a), "l"(b))
#define UNPACK2(lo, hi, s) asm("mov.b64 {%0, %1}, %2;" : "=f"(lo), "=f"(hi) : "l"(s))

// Split-K partials for C[f][e] (plain stores -> deterministic), then reduced.
__device__ float g_Cp[SPLITK][E_DIM * E_DIM];   // 4 MB
__device__ float g_C[E_DIM * E_DIM];            // 256 KB

// ---------------------------------------------------------------------------
// Kernel 1: partial C.  C[f,e] = sum_p Wv[c(p), f] * Wp[e, p]
//   p = d*H + h (Wp-native), c(p) = (p&3)*256 + (p>>2).  Both loads coalesced.
// 64x64 tile, 4x4 micro-tile (f32x2 along f), 256 thr, grid (4,4,16).
// Double-buffered smem: ONE __syncthreads per k-iter.
// ---------------------------------------------------------------------------
__global__ __launch_bounds__(256) void build_C_kernel(
    const float* __restrict__ Wv,   // [EH, E] row-major
    const float* __restrict__ Wp)   // [E, EH] row-major
{
    __shared__ __align__(16) float sA[2][KSTEP][64];   // [buf][p_local][f_local]
    __shared__ __align__(16) float sB[2][KSTEP][68];   // [buf][p_local][e_local]

    const int tid = threadIdx.x;
    const int tx  = tid & 15;       // f group
    const int ty  = tid >> 4;       // e group
    const int f0  = blockIdx.x * 64;
    const int e0  = blockIdx.y * 64;
    const int p0  = blockIdx.z * PCHUNK;

    u64 acc01[4], acc23[4];
    #pragma unroll
    for (int j = 0; j < 4; j++) { PACK2(acc01[j], 0.f, 0.f); PACK2(acc23[j], 0.f, 0.f); }

    const int lA_pc = tid >> 4;            // 0..15
    const int lA_f4 = (tid & 15) * 4;
    const int lB_e  = tid >> 2;            // 0..63
    const int lB_p4 = (tid & 3) * 4;

    // load k-tile 0 into buffer 0
    {
        int p = p0 + lA_pc;
        int c = ((p & 3) << 8) + (p >> 2);
        float4 pa = *(const float4*)&Wv[c * E_DIM + f0 + lA_f4];
        float4 pb = *(const float4*)&Wp[(e0 + lB_e) * EH_DIM + p0 + lB_p4];
        *(float4*)&sA[0][lA_pc][lA_f4] = pa;
        sB[0][lB_p4 + 0][lB_e] = pb.x;
        sB[0][lB_p4 + 1][lB_e] = pb.y;
        sB[0][lB_p4 + 2][lB_e] = pb.z;
        sB[0][lB_p4 + 3][lB_e] = pb.w;
    }
    __syncthreads();

    #pragma unroll
    for (int it = 0; it < PCHUNK / KSTEP; it++) {
        const int cur = it & 1;

        // issue next tile's LDGs first (latency overlapped with compute)
        float4 pa, pb;
        if (it < PCHUNK / KSTEP - 1) {
            int p = p0 + (it + 1) * KSTEP + lA_pc;
            int c = ((p & 3) << 8) + (p >> 2);
            pa = *(const float4*)&Wv[c * E_DIM + f0 + lA_f4];
            pb = *(const float4*)&Wp[(e0 + lB_e) * EH_DIM + p0 + (it + 1) * KSTEP + lB_p4];
        }

        #pragma unroll
        for (int ps = 0; ps < KSTEP; ps++) {
            float4 a = *(float4*)&sA[cur][ps][tx * 4];
            float4 b = *(float4*)&sB[cur][ps][ty * 4];
            u64 a01, a23, bd0, bd1, bd2, bd3;
            PACK2(a01, a.x, a.y);
            PACK2(a23, a.z, a.w);
            PACK2(bd0, b.x, b.x); FMA2(acc01[0], a01, bd0); FMA2(acc23[0], a23, bd0);
            PACK2(bd1, b.y, b.y); FMA2(acc01[1], a01, bd1); FMA2(acc23[1], a23, bd1);
            PACK2(bd2, b.z, b.z); FMA2(acc01[2], a01, bd2); FMA2(acc23[2], a23, bd2);
            PACK2(bd3, b.w, b.w); FMA2(acc01[3], a01, bd3); FMA2(acc23[3], a23, bd3);
        }

        if (it < PCHUNK / KSTEP - 1) {   // fill the other buffer, then ONE sync
            *(float4*)&sA[cur ^ 1][lA_pc][lA_f4] = pa;
            sB[cur ^ 1][lB_p4 + 0][lB_e] = pb.x;
            sB[cur ^ 1][lB_p4 + 1][lB_e] = pb.y;
            sB[cur ^ 1][lB_p4 + 2][lB_e] = pb.z;
            sB[cur ^ 1][lB_p4 + 3][lB_e] = pb.w;
            __syncthreads();
        }
    }

    // epilogue: unpack 16 results, store 4 x STG.128
    float r[4][4];
    #pragma unroll
    for (int j = 0; j < 4; j++) {
        UNPACK2(r[0][j], r[1][j], acc01[j]);
        UNPACK2(r[2][j], r[3][j], acc23[j]);
    }
    float* dst = &g_Cp[blockIdx.z][0];
    #pragma unroll
    for (int i = 0; i < 4; i++) {
        int f = f0 + tx * 4 + i;
        *(float4*)&dst[f * E_DIM + e0 + ty * 4] =
            make_float4(r[i][0], r[i][1], r[i][2], r[i][3]);
    }
}

// ---------------------------------------------------------------------------
// Kernel 2: g_C = sum_z g_Cp[z]   (fixed z order -> deterministic)
// PDL consumer: launches during build_C; waits only before touching g_Cp.
// ---------------------------------------------------------------------------
__global__ __launch_bounds__(128) void reduce_C_kernel()
{
    cudaGridDependencySynchronize();       // all build_C writes visible
    int idx4 = (blockIdx.x * 128 + threadIdx.x) * 4;   // covers 65536 floats
    float4 s = make_float4(0.f, 0.f, 0.f, 0.f);
    #pragma unroll
    for (int z0 = 0; z0 < SPLITK; z0 += 8) {
        float4 v[8];
        #pragma unroll
        for (int z = 0; z < 8; z++)
            v[z] = *(const float4*)&g_Cp[z0 + z][idx4];
        #pragma unroll
        for (int z = 0; z < 8; z++) {
            s.x += v[z].x; s.y += v[z].y; s.z += v[z].z; s.w += v[z].w;
        }
    }
    *(float4*)&g_C[idx4] = s;
}

// ---------------------------------------------------------------------------
// Kernel 3: out[m,e] = sum_f values[m,f] * C[f,e]
// 32x32 tile, 2x2 micro (f32x2 along m), 256 thr, grid (8,16) = 128 CTAs.
// PDL consumer: values prefetch happens BEFORE the dependency sync.
// ---------------------------------------------------------------------------
__global__ __launch_bounds__(256) void gemm_out_kernel(
    const float* __restrict__ values,   // [BT, E]
    float* __restrict__ out)            // [BT, E]
{
    __shared__ __align__(8) float sV[16][34];   // [f_local][m]
    __shared__ __align__(8) float sC[16][34];   // [f_local][e]

    const int tid = threadIdx.x;
    const int tx  = tid & 15;      // e pair
    const int ty  = tid >> 4;      // m pair
    const int e0  = blockIdx.x * 32;
    const int m0  = blockIdx.y * 32;

    u64 accj0, accj1;
    PACK2(accj0, 0.f, 0.f);
    PACK2(accj1, 0.f, 0.f);

    const int lV_m  = tid >> 3;
    const int lV_f2 = (tid & 7) * 2;
    const int lC_f  = tid >> 4;
    const int lC_e2 = (tid & 15) * 2;

    // independent prologue: runs concurrently with reduce_C via PDL
    float2 pv = *(const float2*)&values[(m0 + lV_m) * E_DIM + lV_f2];

    cudaGridDependencySynchronize();       // g_C now valid
    float2 pc = *(const float2*)&g_C[lC_f * E_DIM + e0 + lC_e2];

    #pragma unroll
    for (int it = 0; it < E_DIM / 16; it++) {
        sV[lV_f2][lV_m]     = pv.x;        // transposed store
        sV[lV_f2 + 1][lV_m] = pv.y;
        *(float2*)&sC[lC_f][lC_e2] = pc;
        __syncthreads();

        if (it < E_DIM / 16 - 1) {
            int f0 = (it + 1) * 16;
            pv = *(const float2*)&values[(m0 + lV_m) * E_DIM + f0 + lV_f2];
            pc = *(const float2*)&g_C[(f0 + lC_f) * E_DIM + e0 + lC_e2];
        }

        #pragma unroll
        for (int ps = 0; ps < 16; ps++) {
            float2 a = *(float2*)&sV[ps][ty * 2];
            float2 b = *(float2*)&sC[ps][tx * 2];
            u64 a01, bd0, bd1;
            PACK2(a01, a.x, a.y);
            PACK2(bd0, b.x, b.x); FMA2(accj0, a01, bd0);
            PACK2(bd1, b.y, b.y); FMA2(accj1, a01, bd1);
        }
        __syncthreads();
    }

    float o00, o10, o01, o11;
    UNPACK2(o00, o10, accj0);
    UNPACK2(o01, o11, accj1);
    *(float2*)&out[(m0 + ty * 2) * E_DIM + e0 + tx * 2]     = make_float2(o00, o01);
    *(float2*)&out[(m0 + ty * 2 + 1) * E_DIM + e0 + tx * 2] = make_float2(o10, o11);
}

// ---------------------------------------------------------------------------
// softmax over w sums to 1 => out = Vh; only values, Wv, Wp matter.
// Inputs: 0=pos_emb, 1=values, 2=ln_w, 3=ln_b, 4=Wq, 5=Wk, 6=Wv, 7=Wp.
// Consumers launch with ProgrammaticStreamSerialization (PDL) so their
// launch latency + prologue overlap the predecessor's execution.
// ---------------------------------------------------------------------------
extern "C" void kernel_launch(void* const* d_in, const int* in_sizes, int n_in,
                              void* d_out, int out_size)
{
    const float* values = (const float*)d_in[1];
    const float* Wv     = (const float*)d_in[6];
    const float* Wp     = (const float*)d_in[7];
    float* out          = (float*)d_out;

    build_C_kernel<<<dim3(4, 4, SPLITK), 256>>>(Wv, Wp);

    cudaLaunchAttribute attr[1];
    attr[0].id = cudaLaunchAttributeProgrammaticStreamSerialization;
    attr[0].val.programmaticStreamSerializationAllowed = 1;

    {
        cudaLaunchConfig_t cfg = {};
        cfg.gridDim  = dim3(128, 1, 1);
        cfg.blockDim = dim3(128, 1, 1);
        cfg.stream   = 0;
        cfg.attrs    = attr;
        cfg.numAttrs = 1;
        cudaLaunchKernelEx(&cfg, reduce_C_kernel);
    }
    {
        cudaLaunchConfig_t cfg = {};
        cfg.gridDim  = dim3(8, 16, 1);
        cfg.blockDim = dim3(256, 1, 1);
        cfg.stream   = 0;
        cfg.attrs    = attr;
        cfg.numAttrs = 1;
        cudaLaunchKernelEx(&cfg, gemm_out_kernel, values, out);
    }
}